// round 2
// baseline (speedup 1.0000x reference)
#include <cuda_runtime.h>
#include <cstddef>

#define SB 4          // batch
#define SS 1024       // seq
#define HID 768
#define NH 6          // heads
#define HD 64         // head dim
#define AH 384        // NH*HD
#define KS 9
#define PAD 4
#define BSROWS (SB*SS)   // 4096
#define OUTW (2*AH)      // 768

// ---------------- scratch (device globals; no allocation) ----------------
__device__ float g_mq [BSROWS*AH];
__device__ float g_mk [BSROWS*AH];
__device__ float g_mv [BSROWS*AH];
__device__ float g_co [BSROWS*AH];
__device__ float g_mkc[BSROWS*AH];
__device__ float g_dw [BSROWS*HID];
__device__ float g_ca [BSROWS*AH];
__device__ float g_ck [BSROWS*(NH*KS)];
__device__ float g_pwT[HID*AH];
__device__ float g_tdsm[SB*SS];

// ---------------- generic tiled SGEMM: C[M=4096,N] = A[M,K] @ B[K,N] + bias ----------------
__device__ __forceinline__ void gemm64_body(const float* __restrict__ A,
                                            const float* __restrict__ Bm,
                                            const float* __restrict__ bias,
                                            float* __restrict__ C,
                                            int N, int K) {
    __shared__ float As[16][68];   // [k][m], padded
    __shared__ float Bs[16][64];   // [k][n]
    const int tid = threadIdx.x;           // 256 threads
    const int tx = tid & 15, ty = tid >> 4;
    const int bm = blockIdx.y * 64, bn = blockIdx.x * 64;
    float acc[4][4] = {};
    for (int k0 = 0; k0 < K; k0 += 16) {
        #pragma unroll
        for (int i = 0; i < 4; i++) {
            int e = tid + 256 * i;
            int r = e >> 4, c = e & 15;            // A tile: 64 rows x 16 k
            As[c][r] = A[(size_t)(bm + r) * K + (k0 + c)];
            int r2 = e >> 6, c2 = e & 63;          // B tile: 16 k x 64 n
            int gn = bn + c2;
            Bs[r2][c2] = (gn < N) ? Bm[(size_t)(k0 + r2) * N + gn] : 0.f;
        }
        __syncthreads();
        #pragma unroll
        for (int kk = 0; kk < 16; kk++) {
            float a0 = As[kk][ty*4+0], a1 = As[kk][ty*4+1], a2 = As[kk][ty*4+2], a3 = As[kk][ty*4+3];
            float b0 = Bs[kk][tx*4+0], b1 = Bs[kk][tx*4+1], b2 = Bs[kk][tx*4+2], b3 = Bs[kk][tx*4+3];
            acc[0][0] += a0*b0; acc[0][1] += a0*b1; acc[0][2] += a0*b2; acc[0][3] += a0*b3;
            acc[1][0] += a1*b0; acc[1][1] += a1*b1; acc[1][2] += a1*b2; acc[1][3] += a1*b3;
            acc[2][0] += a2*b0; acc[2][1] += a2*b1; acc[2][2] += a2*b2; acc[2][3] += a2*b3;
            acc[3][0] += a3*b0; acc[3][1] += a3*b1; acc[3][2] += a3*b2; acc[3][3] += a3*b3;
        }
        __syncthreads();
    }
    #pragma unroll
    for (int i = 0; i < 4; i++) {
        int gm = bm + ty*4 + i;
        #pragma unroll
        for (int j = 0; j < 4; j++) {
            int gn = bn + tx*4 + j;
            if (gn < N) C[(size_t)gm * N + gn] = acc[i][j] + (bias ? bias[gn] : 0.f);
        }
    }
}

__global__ __launch_bounds__(256) void k_gemm_mq(const float* A, const float* W) { gemm64_body(A, W, nullptr, g_mq, AH, HID); }
__global__ __launch_bounds__(256) void k_gemm_mk(const float* A, const float* W) { gemm64_body(A, W, nullptr, g_mk, AH, HID); }
__global__ __launch_bounds__(256) void k_gemm_mv(const float* A, const float* W) { gemm64_body(A, W, nullptr, g_mv, AH, HID); }
__global__ __launch_bounds__(256) void k_gemm_co(const float* A, const float* W, const float* bias) { gemm64_body(A, W, bias, g_co, AH, HID); }
__global__ __launch_bounds__(256) void k_gemm_mkc(const float* sep_b) { gemm64_body(g_dw, g_pwT, sep_b, g_mkc, AH, HID); }
__global__ __launch_bounds__(256) void k_gemm_ck(const float* ckW, const float* ckb) { gemm64_body(g_ca, ckW, ckb, g_ck, NH*KS, AH); }

// ---------------- depthwise conv over sequence dim of K ----------------
__global__ void dwconv_kernel(const float* __restrict__ Kin, const float* __restrict__ dww) {
    int idx = blockIdx.x * blockDim.x + threadIdx.x;
    if (idx >= BSROWS * HID) return;
    int c = idx % HID;
    int s = (idx / HID) & (SS - 1);
    int b = idx / (HID * SS);
    float acc = 0.f;
    #pragma unroll
    for (int t = 0; t < KS; t++) {
        int sj = s + t - PAD;
        if (sj >= 0 && sj < SS)
            acc += Kin[((size_t)(b * SS + sj)) * HID + c] * dww[c * KS + t];
    }
    g_dw[idx] = acc;
}

// pw_w is (AH, HID); we need (HID, AH) for the GEMM
__global__ void transpose_pw(const float* __restrict__ pw) {
    int idx = blockIdx.x * blockDim.x + threadIdx.x;
    if (idx >= HID * AH) return;
    int o = idx % AH, c = idx / AH;
    g_pwT[idx] = pw[(size_t)o * HID + c];
}

__global__ void mul_kernel() {
    int idx = blockIdx.x * blockDim.x + threadIdx.x;
    if (idx < BSROWS * AH) g_ca[idx] = g_mkc[idx] * g_mq[idx];
}

// ---------------- dynamic-span conv output (softmax over 9 taps + gather) ----------------
__global__ __launch_bounds__(384) void convout_kernel(float* __restrict__ out) {
    int bs = blockIdx.x;                    // 0..4095
    int tid = threadIdx.x;                  // 384 = NH*HD
    int h = tid >> 6, d = tid & 63;
    const float* cr = g_ck + (size_t)bs * (NH*KS) + h * KS;
    float w[KS];
    float mx = -3.4e38f;
    #pragma unroll
    for (int t = 0; t < KS; t++) { w[t] = cr[t]; mx = fmaxf(mx, w[t]); }
    float sm = 0.f;
    #pragma unroll
    for (int t = 0; t < KS; t++) { w[t] = expf(w[t] - mx); sm += w[t]; }
    float inv = 1.f / sm;
    int b = bs >> 10, s = bs & (SS - 1);
    float acc = 0.f;
    #pragma unroll
    for (int t = 0; t < KS; t++) {
        int sj = s + t - PAD;
        if (sj >= 0 && sj < SS)
            acc += w[t] * inv * g_co[((size_t)(b * SS + sj)) * AH + h * HD + d];
    }
    out[(size_t)bs * OUTW + AH + h * HD + d] = acc;
}

// ---------------- td softmax (batch-only; independent of head and query row) ----------------
__global__ __launch_bounds__(256) void tdsm_kernel(const float* __restrict__ td, const int* __restrict__ mask) {
    int b = blockIdx.x;
    int tid = threadIdx.x;
    __shared__ float s_red[256];
    const float* tr = td + b * SS;
    const int* mr = mask + b * SS;
    float ss = 0.f;
    for (int j = tid; j < SS; j += 256) { float v = tr[j]; ss += v * v; }
    s_red[tid] = ss; __syncthreads();
    for (int off = 128; off > 0; off >>= 1) { if (tid < off) s_red[tid] += s_red[tid + off]; __syncthreads(); }
    float inv = 1.f / fmaxf(sqrtf(s_red[0]), 1e-12f);
    __syncthreads();
    float mx = -3.4e38f;
    for (int j = tid; j < SS; j += 256) { float v = mr[j] ? tr[j] * inv : -1e4f; mx = fmaxf(mx, v); }
    s_red[tid] = mx; __syncthreads();
    for (int off = 128; off > 0; off >>= 1) { if (tid < off) s_red[tid] = fmaxf(s_red[tid], s_red[tid + off]); __syncthreads(); }
    mx = s_red[0]; __syncthreads();
    float es = 0.f;
    for (int j = tid; j < SS; j += 256) { float v = mr[j] ? tr[j] * inv : -1e4f; es += expf(v - mx); }
    s_red[tid] = es; __syncthreads();
    for (int off = 128; off > 0; off >>= 1) { if (tid < off) s_red[tid] += s_red[tid + off]; __syncthreads(); }
    es = s_red[0]; __syncthreads();
    float einv = 1.f / es;
    for (int j = tid; j < SS; j += 256) {
        float v = mr[j] ? tr[j] * inv : -1e4f;
        g_tdsm[b * SS + j] = expf(v - mx) * einv;
    }
}

// ---------------- attention with distance decay: one block per (b,h,i) row ----------------
__global__ __launch_bounds__(256) void attn_kernel(const int* __restrict__ mask,
                                                   const float* __restrict__ gammas,
                                                   float* __restrict__ out) {
    const int tid = threadIdx.x;
    const int row = blockIdx.x;            // b*H*S + h*S + i
    const int i = row & (SS - 1);
    const int bh = row >> 10;
    const int h = bh % NH;
    const int b = bh / NH;

    __shared__ __align__(16) float s_q[HD];
    __shared__ float s_sc[SS];
    __shared__ float s_p[SS];
    __shared__ float s_red[256];

    const float* qp = g_mq + ((size_t)(b * SS + i)) * AH + h * HD;
    if (tid < HD) s_q[tid] = qp[tid];
    __syncthreads();

    const float* kbase = g_mk + (size_t)b * SS * AH + h * HD;
    const int* mrow = mask + b * SS;

    // scores = q . k / sqrt(D)
    for (int j = tid; j < SS; j += 256) {
        const float4* kp = reinterpret_cast<const float4*>(kbase + (size_t)j * AH);
        const float4* qq = reinterpret_cast<const float4*>(s_q);
        float d = 0.f;
        #pragma unroll
        for (int u = 0; u < 16; u++) {
            float4 kv = kp[u]; float4 qv = qq[u];
            d += kv.x * qv.x; d += kv.y * qv.y; d += kv.z * qv.z; d += kv.w * qv.w;
        }
        s_sc[j] = d * 0.125f;
    }
    __syncthreads();

    // masked softmax -> p
    float mx = -3.4e38f;
    for (int j = tid; j < SS; j += 256) {
        float v = mrow[j] ? s_sc[j] : -1e8f;
        mx = fmaxf(mx, v);
    }
    s_red[tid] = mx; __syncthreads();
    for (int off = 128; off > 0; off >>= 1) { if (tid < off) s_red[tid] = fmaxf(s_red[tid], s_red[tid + off]); __syncthreads(); }
    mx = s_red[0]; __syncthreads();
    float sm = 0.f;
    for (int j = tid; j < SS; j += 256) {
        float e = mrow[j] ? expf(s_sc[j] - mx) : 0.f;
        s_p[j] = e; sm += e;
    }
    s_red[tid] = sm; __syncthreads();
    for (int off = 128; off > 0; off >>= 1) { if (tid < off) s_red[tid] += s_red[tid + off]; __syncthreads(); }
    sm = s_red[0]; __syncthreads();
    float inv = (sm > 0.f) ? (1.f / sm) : 0.f;

    // inclusive cumsum of p over j (contiguous 4-per-thread + block scan)
    const int base = tid * 4;
    float r0 = s_p[base + 0] * inv;
    float r1 = s_p[base + 1] * inv;
    float r2 = s_p[base + 2] * inv;
    float r3 = s_p[base + 3] * inv;
    float c0 = r0, c1 = c0 + r1, c2 = c1 + r2, c3 = c2 + r3;
    s_red[tid] = c3;
    __syncthreads();
    #pragma unroll
    for (int off = 1; off < 256; off <<= 1) {
        float v = (tid >= off) ? s_red[tid - off] : 0.f;
        __syncthreads();
        s_red[tid] += v;
        __syncthreads();
    }
    const float total = s_red[255];
    const float pref = s_red[tid] - c3;
    __syncthreads();                 // everyone done reading s_red before reuse
    s_p[base + 0] = pref + c0;       // distcum (only read back by this thread)
    s_p[base + 1] = pref + c1;
    s_p[base + 2] = pref + c2;
    s_p[base + 3] = pref + c3;

    // total_effect and rescaled scores
    const float gamma_h = -log1pf(expf(gammas[h]));   // -softplus
    const float* tdr = g_tdsm + b * SS;
    float mx2 = -3.4e38f;
    #pragma unroll
    for (int u = 0; u < 4; u++) {
        int j = base + u;
        float rem = total - s_p[j];
        float posd = fabsf((float)(j - i));
        float ds = sqrtf(fmaxf(rem * posd, 0.f));
        float te = expf(ds * gamma_h);
        te = fminf(fmaxf(te, 1e-5f), 1e5f);
        if (j < i) te -= tdr[j];
        float v = mrow[j] ? s_sc[j] * te : -1e8f;
        s_sc[j] = v;
        mx2 = fmaxf(mx2, v);
    }
    s_red[tid] = mx2; __syncthreads();
    for (int off = 128; off > 0; off >>= 1) { if (tid < off) s_red[tid] = fmaxf(s_red[tid], s_red[tid + off]); __syncthreads(); }
    mx2 = s_red[0]; __syncthreads();
    float sm2 = 0.f;
    #pragma unroll
    for (int u = 0; u < 4; u++) {
        int j = base + u;
        float e = expf(s_sc[j] - mx2);
        s_p[j] = e; sm2 += e;
    }
    s_red[tid] = sm2; __syncthreads();
    for (int off = 128; off > 0; off >>= 1) { if (tid < off) s_red[tid] += s_red[tid + off]; __syncthreads(); }
    sm2 = s_red[0]; __syncthreads();
    float inv2 = 1.f / sm2;
    #pragma unroll
    for (int u = 0; u < 4; u++) s_p[base + u] *= inv2;
    __syncthreads();

    // ctx = probs @ V  (4 groups x 64 lanes)
    const int d = tid & 63, g = tid >> 6;
    const float* vb = g_mv + (size_t)b * SS * AH + h * HD + d;
    float acc = 0.f;
    for (int j = g; j < SS; j += 4) acc += s_p[j] * vb[(size_t)j * AH];
    s_red[tid] = acc; __syncthreads();
    if (tid < 64) {
        float r = s_red[tid] + s_red[tid + 64] + s_red[tid + 128] + s_red[tid + 192];
        out[((size_t)(b * SS + i)) * OUTW + h * HD + tid] = r;
    }
}

// ---------------- launch ----------------
extern "C" void kernel_launch(void* const* d_in, const int* in_sizes, int n_in,
                              void* d_out, int out_size) {
    const float* Q     = (const float*)d_in[0];
    const float* Kin   = (const float*)d_in[1];
    const float* V     = (const float*)d_in[2];
    const float* td    = (const float*)d_in[3];
    const int*   mask  = (const int*)  d_in[4];
    const float* Wq    = (const float*)d_in[5];
    const float* Wk    = (const float*)d_in[6];
    const float* Wv    = (const float*)d_in[7];
    const float* dw_w  = (const float*)d_in[8];
    const float* pw_w  = (const float*)d_in[9];
    const float* sep_b = (const float*)d_in[10];
    const float* ck_W  = (const float*)d_in[11];
    const float* ck_b  = (const float*)d_in[12];
    const float* co_W  = (const float*)d_in[13];
    const float* co_b  = (const float*)d_in[14];
    const float* gammas= (const float*)d_in[15];
    float* out = (float*)d_out;

    dim3 gg((AH + 63) / 64, BSROWS / 64);       // (6, 64)
    k_gemm_mq<<<gg, 256>>>(Q,   Wq);
    k_gemm_mk<<<gg, 256>>>(Kin, Wk);
    k_gemm_mv<<<gg, 256>>>(V,   Wv);
    k_gemm_co<<<gg, 256>>>(V,   co_W, co_b);

    dwconv_kernel<<<(BSROWS * HID + 255) / 256, 256>>>(Kin, dw_w);
    transpose_pw<<<(HID * AH + 255) / 256, 256>>>(pw_w);
    k_gemm_mkc<<<gg, 256>>>(sep_b);

    mul_kernel<<<(BSROWS * AH + 255) / 256, 256>>>();
    dim3 gck((NH * KS + 63) / 64, BSROWS / 64); // (1, 64)
    k_gemm_ck<<<gck, 256>>>(ck_W, ck_b);
    convout_kernel<<<BSROWS, 384>>>(out);

    tdsm_kernel<<<SB, 256>>>(td, mask);
    attn_kernel<<<SB * NH * SS, 256>>>(mask, gammas, out);
}

// round 3
// speedup vs baseline: 2.5385x; 2.5385x over previous
#include <cuda_runtime.h>
#include <cstddef>

#define SB 4          // batch
#define SS 1024       // seq
#define HID 768
#define NH 6          // heads
#define HD 64         // head dim
#define AH 384        // NH*HD
#define KS 9
#define PAD 4
#define BSROWS (SB*SS)   // 4096
#define OUTW (2*AH)      // 768
#define NBH (SB*NH)      // 24

// ---------------- scratch (device globals; no allocation) ----------------
__device__ float g_mq [BSROWS*AH];
__device__ float g_mk [BSROWS*AH];
__device__ float g_mv [BSROWS*AH];
__device__ float g_co [BSROWS*AH];
__device__ float g_mkc[BSROWS*AH];
__device__ float g_dw [BSROWS*HID];
__device__ float g_ca [BSROWS*AH];
__device__ float g_ck [BSROWS*(NH*KS)];
__device__ float g_pwT[HID*AH];
__device__ float g_tdsm[SB*SS];
__device__ float g_sc [(size_t)NBH*SS*SS];   // scores / probs, 100.7 MB

// ---------------- generic tiled SGEMM: C[M=4096,N] = A[M,K] @ B[K,N] + bias ----------------
__device__ __forceinline__ void gemm64_body(const float* __restrict__ A,
                                            const float* __restrict__ Bm,
                                            const float* __restrict__ bias,
                                            float* __restrict__ C,
                                            int N, int K) {
    __shared__ float As[16][68];   // [k][m], padded
    __shared__ float Bs[16][64];   // [k][n]
    const int tid = threadIdx.x;           // 256 threads
    const int tx = tid & 15, ty = tid >> 4;
    const int bm = blockIdx.y * 64, bn = blockIdx.x * 64;
    float acc[4][4] = {};
    for (int k0 = 0; k0 < K; k0 += 16) {
        #pragma unroll
        for (int i = 0; i < 4; i++) {
            int e = tid + 256 * i;
            int r = e >> 4, c = e & 15;            // A tile: 64 rows x 16 k
            As[c][r] = A[(size_t)(bm + r) * K + (k0 + c)];
            int r2 = e >> 6, c2 = e & 63;          // B tile: 16 k x 64 n
            int gn = bn + c2;
            Bs[r2][c2] = (gn < N) ? Bm[(size_t)(k0 + r2) * N + gn] : 0.f;
        }
        __syncthreads();
        #pragma unroll
        for (int kk = 0; kk < 16; kk++) {
            float a0 = As[kk][ty*4+0], a1 = As[kk][ty*4+1], a2 = As[kk][ty*4+2], a3 = As[kk][ty*4+3];
            float b0 = Bs[kk][tx*4+0], b1 = Bs[kk][tx*4+1], b2 = Bs[kk][tx*4+2], b3 = Bs[kk][tx*4+3];
            acc[0][0] += a0*b0; acc[0][1] += a0*b1; acc[0][2] += a0*b2; acc[0][3] += a0*b3;
            acc[1][0] += a1*b0; acc[1][1] += a1*b1; acc[1][2] += a1*b2; acc[1][3] += a1*b3;
            acc[2][0] += a2*b0; acc[2][1] += a2*b1; acc[2][2] += a2*b2; acc[2][3] += a2*b3;
            acc[3][0] += a3*b0; acc[3][1] += a3*b1; acc[3][2] += a3*b2; acc[3][3] += a3*b3;
        }
        __syncthreads();
    }
    #pragma unroll
    for (int i = 0; i < 4; i++) {
        int gm = bm + ty*4 + i;
        #pragma unroll
        for (int j = 0; j < 4; j++) {
            int gn = bn + tx*4 + j;
            if (gn < N) C[(size_t)gm * N + gn] = acc[i][j] + (bias ? bias[gn] : 0.f);
        }
    }
}

__global__ __launch_bounds__(256) void k_gemm_mq(const float* A, const float* W) { gemm64_body(A, W, nullptr, g_mq, AH, HID); }
__global__ __launch_bounds__(256) void k_gemm_mk(const float* A, const float* W) { gemm64_body(A, W, nullptr, g_mk, AH, HID); }
__global__ __launch_bounds__(256) void k_gemm_mv(const float* A, const float* W) { gemm64_body(A, W, nullptr, g_mv, AH, HID); }
__global__ __launch_bounds__(256) void k_gemm_co(const float* A, const float* W, const float* bias) { gemm64_body(A, W, bias, g_co, AH, HID); }
__global__ __launch_bounds__(256) void k_gemm_mkc(const float* sep_b) { gemm64_body(g_dw, g_pwT, sep_b, g_mkc, AH, HID); }
__global__ __launch_bounds__(256) void k_gemm_ck(const float* ckW, const float* ckb) { gemm64_body(g_ca, ckW, ckb, g_ck, NH*KS, AH); }

// ---------------- QK^T batched: scores[bh, i, j] = q_i . k_j / 8 ----------------
__global__ __launch_bounds__(256) void qk_kernel() {
    const int bh = blockIdx.z;           // 0..23
    const int b = bh / NH, h = bh % NH;
    const int bi = blockIdx.y * 64, bj = blockIdx.x * 64;
    __shared__ float Qs[HD][65];         // [d][i]
    __shared__ float Ks[HD][65];         // [d][j]
    const int tid = threadIdx.x;
    const float* qb = g_mq + (size_t)b * SS * AH + h * HD;
    const float* kb = g_mk + (size_t)b * SS * AH + h * HD;
    #pragma unroll
    for (int r = 0; r < 16; r++) {
        int e = tid + 256 * r;
        int i = e >> 6, d = e & 63;
        Qs[d][i] = qb[(size_t)(bi + i) * AH + d];
        Ks[d][i] = kb[(size_t)(bj + i) * AH + d];
    }
    __syncthreads();
    const int tx = tid & 15, ty = tid >> 4;
    float acc[4][4] = {};
    #pragma unroll 16
    for (int d = 0; d < HD; d++) {
        float a0 = Qs[d][ty*4+0], a1 = Qs[d][ty*4+1], a2 = Qs[d][ty*4+2], a3 = Qs[d][ty*4+3];
        float b0 = Ks[d][tx*4+0], b1 = Ks[d][tx*4+1], b2 = Ks[d][tx*4+2], b3 = Ks[d][tx*4+3];
        acc[0][0] += a0*b0; acc[0][1] += a0*b1; acc[0][2] += a0*b2; acc[0][3] += a0*b3;
        acc[1][0] += a1*b0; acc[1][1] += a1*b1; acc[1][2] += a1*b2; acc[1][3] += a1*b3;
        acc[2][0] += a2*b0; acc[2][1] += a2*b1; acc[2][2] += a2*b2; acc[2][3] += a2*b3;
        acc[3][0] += a3*b0; acc[3][1] += a3*b1; acc[3][2] += a3*b2; acc[3][3] += a3*b3;
    }
    float* crow = g_sc + ((size_t)bh * SS) * SS;
    #pragma unroll
    for (int i = 0; i < 4; i++) {
        size_t ro = (size_t)(bi + ty*4 + i) * SS + bj;
        #pragma unroll
        for (int j = 0; j < 4; j++)
            crow[ro + tx*4 + j] = acc[i][j] * 0.125f;
    }
}

// ---------------- P@V batched: ctx[bh, i, d] -> out[:, 0:AH] ----------------
__global__ __launch_bounds__(256) void pv_kernel(float* __restrict__ out) {
    const int bh = blockIdx.y;
    const int b = bh / NH, h = bh % NH;
    const int bi = blockIdx.x * 64;
    __shared__ float As[16][68];   // [k][i]
    __shared__ float Bs[16][64];   // [k][d]
    const int tid = threadIdx.x;
    const int tx = tid & 15, ty = tid >> 4;
    const float* P = g_sc + (size_t)bh * SS * SS;
    const float* vb = g_mv + (size_t)b * SS * AH + h * HD;
    float acc[4][4] = {};
    for (int k0 = 0; k0 < SS; k0 += 16) {
        #pragma unroll
        for (int i = 0; i < 4; i++) {
            int e = tid + 256 * i;
            int r = e >> 4, c = e & 15;
            As[c][r] = P[(size_t)(bi + r) * SS + (k0 + c)];
            int r2 = e >> 6, c2 = e & 63;
            Bs[r2][c2] = vb[(size_t)(k0 + r2) * AH + c2];
        }
        __syncthreads();
        #pragma unroll
        for (int kk = 0; kk < 16; kk++) {
            float a0 = As[kk][ty*4+0], a1 = As[kk][ty*4+1], a2 = As[kk][ty*4+2], a3 = As[kk][ty*4+3];
            float b0 = Bs[kk][tx*4+0], b1 = Bs[kk][tx*4+1], b2 = Bs[kk][tx*4+2], b3 = Bs[kk][tx*4+3];
            acc[0][0] += a0*b0; acc[0][1] += a0*b1; acc[0][2] += a0*b2; acc[0][3] += a0*b3;
            acc[1][0] += a1*b0; acc[1][1] += a1*b1; acc[1][2] += a1*b2; acc[1][3] += a1*b3;
            acc[2][0] += a2*b0; acc[2][1] += a2*b1; acc[2][2] += a2*b2; acc[2][3] += a2*b3;
            acc[3][0] += a3*b0; acc[3][1] += a3*b1; acc[3][2] += a3*b2; acc[3][3] += a3*b3;
        }
        __syncthreads();
    }
    #pragma unroll
    for (int i = 0; i < 4; i++) {
        size_t ro = (size_t)(b * SS + bi + ty*4 + i) * OUTW + h * HD;
        #pragma unroll
        for (int j = 0; j < 4; j++)
            out[ro + tx*4 + j] = acc[i][j];
    }
}

// ---------------- depthwise conv over sequence dim of K ----------------
__global__ void dwconv_kernel(const float* __restrict__ Kin, const float* __restrict__ dww) {
    int idx = blockIdx.x * blockDim.x + threadIdx.x;
    if (idx >= BSROWS * HID) return;
    int c = idx % HID;
    int s = (idx / HID) & (SS - 1);
    int b = idx / (HID * SS);
    float acc = 0.f;
    #pragma unroll
    for (int t = 0; t < KS; t++) {
        int sj = s + t - PAD;
        if (sj >= 0 && sj < SS)
            acc += Kin[((size_t)(b * SS + sj)) * HID + c] * dww[c * KS + t];
    }
    g_dw[idx] = acc;
}

// pw_w is (AH, HID); we need (HID, AH) for the GEMM
__global__ void transpose_pw(const float* __restrict__ pw) {
    int idx = blockIdx.x * blockDim.x + threadIdx.x;
    if (idx >= HID * AH) return;
    int o = idx % AH, c = idx / AH;
    g_pwT[idx] = pw[(size_t)o * HID + c];
}

__global__ void mul_kernel() {
    int idx = blockIdx.x * blockDim.x + threadIdx.x;
    if (idx < BSROWS * AH) g_ca[idx] = g_mkc[idx] * g_mq[idx];
}

// ---------------- dynamic-span conv output (softmax over 9 taps + gather) ----------------
__global__ __launch_bounds__(384) void convout_kernel(float* __restrict__ out) {
    int bs = blockIdx.x;                    // 0..4095
    int tid = threadIdx.x;                  // 384 = NH*HD
    int h = tid >> 6, d = tid & 63;
    const float* cr = g_ck + (size_t)bs * (NH*KS) + h * KS;
    float w[KS];
    float mx = -3.4e38f;
    #pragma unroll
    for (int t = 0; t < KS; t++) { w[t] = cr[t]; mx = fmaxf(mx, w[t]); }
    float sm = 0.f;
    #pragma unroll
    for (int t = 0; t < KS; t++) { w[t] = expf(w[t] - mx); sm += w[t]; }
    float inv = 1.f / sm;
    int b = bs >> 10, s = bs & (SS - 1);
    float acc = 0.f;
    #pragma unroll
    for (int t = 0; t < KS; t++) {
        int sj = s + t - PAD;
        if (sj >= 0 && sj < SS)
            acc += w[t] * inv * g_co[((size_t)(b * SS + sj)) * AH + h * HD + d];
    }
    out[(size_t)bs * OUTW + AH + h * HD + d] = acc;
}

// ---------------- td softmax (batch-only) ----------------
__global__ __launch_bounds__(256) void tdsm_kernel(const float* __restrict__ td, const int* __restrict__ mask) {
    int b = blockIdx.x;
    int tid = threadIdx.x;
    __shared__ float s_red[256];
    const float* tr = td + b * SS;
    const int* mr = mask + b * SS;
    float ss = 0.f;
    for (int j = tid; j < SS; j += 256) { float v = tr[j]; ss += v * v; }
    s_red[tid] = ss; __syncthreads();
    for (int off = 128; off > 0; off >>= 1) { if (tid < off) s_red[tid] += s_red[tid + off]; __syncthreads(); }
    float inv = 1.f / fmaxf(sqrtf(s_red[0]), 1e-12f);
    __syncthreads();
    float mx = -3.4e38f;
    for (int j = tid; j < SS; j += 256) { float v = mr[j] ? tr[j] * inv : -1e4f; mx = fmaxf(mx, v); }
    s_red[tid] = mx; __syncthreads();
    for (int off = 128; off > 0; off >>= 1) { if (tid < off) s_red[tid] = fmaxf(s_red[tid], s_red[tid + off]); __syncthreads(); }
    mx = s_red[0]; __syncthreads();
    float es = 0.f;
    for (int j = tid; j < SS; j += 256) { float v = mr[j] ? tr[j] * inv : -1e4f; es += expf(v - mx); }
    s_red[tid] = es; __syncthreads();
    for (int off = 128; off > 0; off >>= 1) { if (tid < off) s_red[tid] += s_red[tid + off]; __syncthreads(); }
    es = s_red[0]; __syncthreads();
    float einv = 1.f / es;
    for (int j = tid; j < SS; j += 256) {
        float v = mr[j] ? tr[j] * inv : -1e4f;
        g_tdsm[b * SS + j] = expf(v - mx) * einv;
    }
}

// ---------------- per-row: softmax -> cumsum -> decay -> softmax, in place on g_sc ----------------
__global__ __launch_bounds__(256) void row_kernel(const int* __restrict__ mask,
                                                  const float* __restrict__ gammas) {
    const int tid = threadIdx.x;
    const int row = blockIdx.x;            // bh*SS + i
    const int i = row & (SS - 1);
    const int bh = row >> 10;
    const int h = bh % NH;
    const int b = bh / NH;

    __shared__ float s_sc[SS];
    __shared__ float s_p[SS];
    __shared__ float s_red[256];

    float* srow = g_sc + (size_t)row * SS;
    const int* mrow = mask + b * SS;

    for (int j = tid; j < SS; j += 256) s_sc[j] = srow[j];
    __syncthreads();

    // masked softmax -> p
    float mx = -3.4e38f;
    for (int j = tid; j < SS; j += 256) {
        float v = mrow[j] ? s_sc[j] : -1e8f;
        mx = fmaxf(mx, v);
    }
    s_red[tid] = mx; __syncthreads();
    for (int off = 128; off > 0; off >>= 1) { if (tid < off) s_red[tid] = fmaxf(s_red[tid], s_red[tid + off]); __syncthreads(); }
    mx = s_red[0]; __syncthreads();
    float sm = 0.f;
    for (int j = tid; j < SS; j += 256) {
        float e = mrow[j] ? expf(s_sc[j] - mx) : 0.f;
        s_p[j] = e; sm += e;
    }
    s_red[tid] = sm; __syncthreads();
    for (int off = 128; off > 0; off >>= 1) { if (tid < off) s_red[tid] += s_red[tid + off]; __syncthreads(); }
    sm = s_red[0]; __syncthreads();
    float inv = (sm > 0.f) ? (1.f / sm) : 0.f;

    // inclusive cumsum of p over j (4-per-thread + block scan)
    const int base = tid * 4;
    float r0 = s_p[base + 0] * inv;
    float r1 = s_p[base + 1] * inv;
    float r2 = s_p[base + 2] * inv;
    float r3 = s_p[base + 3] * inv;
    float c0 = r0, c1 = c0 + r1, c2 = c1 + r2, c3 = c2 + r3;
    s_red[tid] = c3;
    __syncthreads();
    #pragma unroll
    for (int off = 1; off < 256; off <<= 1) {
        float v = (tid >= off) ? s_red[tid - off] : 0.f;
        __syncthreads();
        s_red[tid] += v;
        __syncthreads();
    }
    const float total = s_red[255];
    const float pref = s_red[tid] - c3;
    __syncthreads();
    s_p[base + 0] = pref + c0;
    s_p[base + 1] = pref + c1;
    s_p[base + 2] = pref + c2;
    s_p[base + 3] = pref + c3;

    // total_effect and rescaled scores
    const float gamma_h = -log1pf(expf(gammas[h]));   // -softplus
    const float* tdr = g_tdsm + b * SS;
    float mx2 = -3.4e38f;
    #pragma unroll
    for (int u = 0; u < 4; u++) {
        int j = base + u;
        float rem = total - s_p[j];
        float posd = fabsf((float)(j - i));
        float ds = sqrtf(fmaxf(rem * posd, 0.f));
        float te = expf(ds * gamma_h);
        te = fminf(fmaxf(te, 1e-5f), 1e5f);
        if (j < i) te -= tdr[j];
        float v = mrow[j] ? s_sc[j] * te : -1e8f;
        s_sc[j] = v;
        mx2 = fmaxf(mx2, v);
    }
    s_red[tid] = mx2; __syncthreads();
    for (int off = 128; off > 0; off >>= 1) { if (tid < off) s_red[tid] = fmaxf(s_red[tid], s_red[tid + off]); __syncthreads(); }
    mx2 = s_red[0]; __syncthreads();
    float sm2 = 0.f;
    #pragma unroll
    for (int u = 0; u < 4; u++) {
        int j = base + u;
        float e = expf(s_sc[j] - mx2);
        s_p[j] = e; sm2 += e;
    }
    s_red[tid] = sm2; __syncthreads();
    for (int off = 128; off > 0; off >>= 1) { if (tid < off) s_red[tid] += s_red[tid + off]; __syncthreads(); }
    sm2 = s_red[0]; __syncthreads();
    float inv2 = 1.f / sm2;
    #pragma unroll
    for (int u = 0; u < 4; u++) srow[base + u] = s_p[base + u] * inv2;
}

// ---------------- launch ----------------
extern "C" void kernel_launch(void* const* d_in, const int* in_sizes, int n_in,
                              void* d_out, int out_size) {
    const float* Q     = (const float*)d_in[0];
    const float* Kin   = (const float*)d_in[1];
    const float* V     = (const float*)d_in[2];
    const float* td    = (const float*)d_in[3];
    const int*   mask  = (const int*)  d_in[4];
    const float* Wq    = (const float*)d_in[5];
    const float* Wk    = (const float*)d_in[6];
    const float* Wv    = (const float*)d_in[7];
    const float* dw_w  = (const float*)d_in[8];
    const float* pw_w  = (const float*)d_in[9];
    const float* sep_b = (const float*)d_in[10];
    const float* ck_W  = (const float*)d_in[11];
    const float* ck_b  = (const float*)d_in[12];
    const float* co_W  = (const float*)d_in[13];
    const float* co_b  = (const float*)d_in[14];
    const float* gammas= (const float*)d_in[15];
    float* out = (float*)d_out;

    dim3 gg((AH + 63) / 64, BSROWS / 64);       // (6, 64)
    k_gemm_mq<<<gg, 256>>>(Q,   Wq);
    k_gemm_mk<<<gg, 256>>>(Kin, Wk);
    k_gemm_mv<<<gg, 256>>>(V,   Wv);
    k_gemm_co<<<gg, 256>>>(V,   co_W, co_b);

    dwconv_kernel<<<(BSROWS * HID + 255) / 256, 256>>>(Kin, dw_w);
    transpose_pw<<<(HID * AH + 255) / 256, 256>>>(pw_w);
    k_gemm_mkc<<<gg, 256>>>(sep_b);

    mul_kernel<<<(BSROWS * AH + 255) / 256, 256>>>();
    dim3 gck((NH * KS + 63) / 64, BSROWS / 64); // (1, 64)
    k_gemm_ck<<<gck, 256>>>(ck_W, ck_b);
    convout_kernel<<<BSROWS, 384>>>(out);

    tdsm_kernel<<<SB, 256>>>(td, mask);
    qk_kernel<<<dim3(SS/64, SS/64, NBH), 256>>>();
    row_kernel<<<NBH * SS, 256>>>(mask, gammas);
    pv_kernel<<<dim3(SS/64, NBH), 256>>>(out);
}